// round 15
// baseline (speedup 1.0000x reference)
#include <cuda_runtime.h>
#include <cstdint>

#define WARPS_PB   8
#define BLOCK_T    256
#define ROWS_W     32                          // rows per warp-stage chunk
#define F4_W       (ROWS_W * 25)               // 800 float4 per stage
#define STAGES     2
#define SMEM_BYTES (WARPS_PB * STAGES * F4_W * 16)   // 204800 B -> 1 block/SM
#define NBLK       148
#define NWARPS     (NBLK * WARPS_PB)           // 1184

// Control block. Zero-initialized at module load; self-reset each launch by
// the last block to copy M (so no per-launch memset node is needed).
struct Ctrl {
    int   flags[20];    // one per producer block (k,i): load-only polling
    int   copied;       // blocks that finished copying M to smem
    int   pad[11];
    float M[200];       // M[k*100 + a]
};
__device__ __align__(16) Ctrl g_ctrl;

__device__ __forceinline__ void mbar_wait(unsigned mbar, unsigned phase) {
    unsigned done;
    asm volatile("{\n\t.reg .pred p;\n\t"
                 "mbarrier.try_wait.parity.acquire.cta.shared::cta.b64 p, [%1], %2;\n\t"
                 "selp.b32 %0, 1, 0, p;\n\t}"
                 : "=r"(done) : "r"(mbar), "r"(phase) : "memory");
    while (!done) {
        asm volatile("{\n\t.reg .pred p;\n\t"
                     "mbarrier.try_wait.parity.acquire.cta.shared::cta.b64 p, [%1], %2, 0x989680;\n\t"
                     "selp.b32 %0, 1, 0, p;\n\t}"
                     : "=r"(done) : "r"(mbar), "r"(phase) : "memory");
    }
}

__global__ void __launch_bounds__(BLOCK_T, 1) fused_kernel(
    const float* __restrict__ x,
    const float* __restrict__ A_real,
    const float* __restrict__ A_imag,
    const float* __restrict__ psi_real,
    const float* __restrict__ psi_imag,
    float2* __restrict__ out,
    int batch)
{
    extern __shared__ __align__(128) float4 sx[];   // [WARPS_PB][STAGES][F4_W]
    __shared__ __align__(16) float sMf[200];
    __shared__ float spr[10], spi[10];
    __shared__ __align__(8) unsigned long long mbar_store[WARPS_PB * STAGES];

    int tid  = threadIdx.x;
    int wid  = tid >> 5;
    int lane = tid & 31;
    int bid  = blockIdx.x;

    unsigned mbar_base = (unsigned)__cvta_generic_to_shared(&mbar_store[0]);
    unsigned wmbar = mbar_base + (wid * STAGES) * 8;
    float4* ws = sx + (size_t)wid * (STAGES * F4_W);

    if (tid < WARPS_PB * STAGES)
        asm volatile("mbarrier.init.shared.b64 [%0], %1;"
                     :: "r"(mbar_base + tid * 8), "r"(1) : "memory");
    if (bid < 20 && tid < 10) { spr[tid] = psi_real[tid]; spi[tid] = psi_imag[tid]; }
    __syncthreads();

    // Balanced contiguous row range for this warp: rows differ by at most 1
    // across all 1184 warps, so every SM drains within ~1 chunk-period.
    int gw    = bid * WARPS_PB + wid;
    int base  = batch / NWARPS;
    int rem   = batch - base * NWARPS;
    int start = gw * base + (gw < rem ? gw : rem);
    int count = base + (gw < rem ? 1 : 0);

    // Issue rows [rowStart, rowStart+rows) into warp-stage s (lane 0 only).
    auto issue = [&](int rowStart, int rows, int s) {
        if (lane == 0) {
            unsigned bytes = (unsigned)rows * 400u;
            unsigned mb = wmbar + s * 8;
            asm volatile("mbarrier.arrive.expect_tx.shared.b64 _, [%0], %1;"
                         :: "r"(mb), "r"(bytes) : "memory");
            unsigned dst = (unsigned)__cvta_generic_to_shared(ws + s * F4_W);
            const float* src = x + (size_t)rowStart * 100;
            asm volatile("cp.async.bulk.shared::cta.global.mbarrier::complete_tx::bytes "
                         "[%0], [%1], %2, [%3];"
                         :: "r"(dst), "l"(src), "r"(bytes), "r"(mb) : "memory");
        }
    };
    auto rows_at = [&](int off) {
        int r = count - off;
        return r > ROWS_W ? ROWS_W : r;
    };

    // Prologue: enqueue both stages first (~205KB/SM in flight).
    if (count > 0)       issue(start, rows_at(0), 0);
    if (count > ROWS_W)  issue(start + ROWS_W, rows_at(ROWS_W), 1);

    // Blocks 0..19: compute the (k,i) partial of M (20 coalesced loads per
    // thread), hidden under the TMA flight. A is read once chip-wide (160KB).
    if (bid < 20) {
        if (tid < 100) {
            int k = bid / 10, i = bid - (bid / 10) * 10;
            int a = tid;
            int abase = ((k * 10 + i) * 10) * 100 + a;
            float acc = 0.0f;
            #pragma unroll
            for (int j = 0; j < 10; j++) {
                float wr = spr[i] * spr[j] + spi[i] * spi[j];
                float wi = spr[i] * spi[j] - spi[i] * spr[j];
                acc = fmaf(wr,  __ldg(A_real + abase + j * 100), acc);
                acc = fmaf(-wi, __ldg(A_imag + abase + j * 100), acc);
            }
            atomicAdd(&g_ctrl.M[k * 100 + a], acc);
            __threadfence();                    // order my adds before the flag
        }
        __syncthreads();
        if (tid == 0) atomicExch(&g_ctrl.flags[bid], 1);
    }

    // All blocks: wait for the 20 producer flags (load-only polling on
    // distinct addresses; shadowed by in-flight TMA copies).
    if (tid < 20) {
        const int* f = &g_ctrl.flags[tid];
        int v;
        do {
            asm volatile("ld.global.cg.b32 %0, [%1];" : "=r"(v) : "l"(f));
            if (!v) __nanosleep(64);
        } while (!v);
    }
    __syncthreads();
    __threadfence();
    if (tid < 200) sMf[tid] = __ldcg(&g_ctrl.M[tid]);   // bypass L1
    __syncthreads();

    // Self-reset: the 148th block to finish copying zeroes the control block
    // for the next graph replay (all blocks have M in smem by then).
    if (tid == 0) {
        __threadfence();                       // my reads precede the arrive
        int v = atomicAdd(&g_ctrl.copied, 1);
        if (v == NBLK - 1) {
            #pragma unroll 4
            for (int q = 0; q < 200; q++) g_ctrl.M[q] = 0.0f;
            #pragma unroll
            for (int q = 0; q < 20; q++) g_ctrl.flags[q] = 0;
            __threadfence();
            g_ctrl.copied = 0;
            __threadfence();
        }
    }
    const float4* sM4 = reinterpret_cast<const float4*>(sMf);   // [50]

    // Steady loop (R13 engine): warp-private 2-stage ring, no block barriers.
    int cnt = 0;
    for (int off = 0; off < count; off += ROWS_W, cnt++) {
        int s = cnt & 1;
        unsigned phase = (cnt >> 1) & 1;
        mbar_wait(wmbar + s * 8, phase);

        int rc = rows_at(off);
        const float4* xr = ws + s * F4_W + lane * 25;
        float s0 = 0.0f, s1 = 0.0f;
        #pragma unroll
        for (int i = 0; i < 25; i++) {
            float4 v  = xr[i];
            float4 m0 = sM4[i];
            float4 m1 = sM4[25 + i];
            s0 = fmaf(v.x, m0.x, s0); s0 = fmaf(v.y, m0.y, s0);
            s0 = fmaf(v.z, m0.z, s0); s0 = fmaf(v.w, m0.w, s0);
            s1 = fmaf(v.x, m1.x, s1); s1 = fmaf(v.y, m1.y, s1);
            s1 = fmaf(v.z, m1.z, s1); s1 = fmaf(v.w, m1.w, s1);
        }
        if (lane < rc) out[start + off + lane] = make_float2(s0, s1);
        __syncwarp();                      // whole warp done reading stage s

        int offn = off + STAGES * ROWS_W;
        if (offn < count) issue(start + offn, rows_at(offn), s);
    }
}

extern "C" void kernel_launch(void* const* d_in, const int* in_sizes, int n_in,
                              void* d_out, int out_size) {
    const float* x        = (const float*)d_in[0];  // [BATCH, 100]
    const float* A_real   = (const float*)d_in[1];  // [2,10,10,100]
    const float* A_imag   = (const float*)d_in[2];  // [2,10,10,100]
    const float* psi_real = (const float*)d_in[3];  // [10]
    const float* psi_imag = (const float*)d_in[4];  // [10]

    int batch = in_sizes[0] / 100;

    static bool attr_done = false;
    if (!attr_done) {
        cudaFuncSetAttribute(fused_kernel,
                             cudaFuncAttributeMaxDynamicSharedMemorySize, SMEM_BYTES);
        attr_done = true;
    }

    fused_kernel<<<NBLK, BLOCK_T, SMEM_BYTES>>>(x, A_real, A_imag,
                                                psi_real, psi_imag,
                                                reinterpret_cast<float2*>(d_out),
                                                batch);
}

// round 16
// speedup vs baseline: 1.0316x; 1.0316x over previous
#include <cuda_runtime.h>
#include <cstdint>

#define WARPS_PB   8
#define BLOCK_T    256
#define ROWS_W     32                          // rows per warp-stage chunk
#define F4_W       (ROWS_W * 25)               // 800 float4 per stage
#define STAGES     2
#define SMEM_BYTES (WARPS_PB * STAGES * F4_W * 16)   // 204800 B -> 1 block/SM
#define NBLK       148
#define NWARPS     (NBLK * WARPS_PB)           // 1184

// Control block. Zero-initialized at module load; self-reset each launch by
// the last block to finish copying M (no per-launch memset node needed).
struct Ctrl {
    int   flags[20];    // one per producer block (k,i): load-only polling
    int   copied;       // blocks that finished copying M to smem
    int   pad[11];
    float M[200];       // M[k*100 + a]
};
__device__ __align__(16) Ctrl g_ctrl;

__device__ __forceinline__ void mbar_wait(unsigned mbar, unsigned phase) {
    unsigned done;
    asm volatile("{\n\t.reg .pred p;\n\t"
                 "mbarrier.try_wait.parity.acquire.cta.shared::cta.b64 p, [%1], %2;\n\t"
                 "selp.b32 %0, 1, 0, p;\n\t}"
                 : "=r"(done) : "r"(mbar), "r"(phase) : "memory");
    while (!done) {
        asm volatile("{\n\t.reg .pred p;\n\t"
                     "mbarrier.try_wait.parity.acquire.cta.shared::cta.b64 p, [%1], %2, 0x989680;\n\t"
                     "selp.b32 %0, 1, 0, p;\n\t}"
                     : "=r"(done) : "r"(mbar), "r"(phase) : "memory");
    }
}

__global__ void __launch_bounds__(BLOCK_T, 1) fused_kernel(
    const float* __restrict__ x,
    const float* __restrict__ A_real,
    const float* __restrict__ A_imag,
    const float* __restrict__ psi_real,
    const float* __restrict__ psi_imag,
    float2* __restrict__ out,
    int batch, int nchunks)
{
    extern __shared__ __align__(128) float4 sx[];   // [WARPS_PB][STAGES][F4_W]
    __shared__ __align__(16) float sMf[200];
    __shared__ float spr[10], spi[10];
    __shared__ __align__(8) unsigned long long mbar_store[WARPS_PB * STAGES];

    int tid  = threadIdx.x;
    int wid  = tid >> 5;
    int lane = tid & 31;
    int bid  = blockIdx.x;

    unsigned mbar_base = (unsigned)__cvta_generic_to_shared(&mbar_store[0]);
    unsigned wmbar = mbar_base + (wid * STAGES) * 8;
    float4* ws = sx + (size_t)wid * (STAGES * F4_W);

    if (tid < WARPS_PB * STAGES)
        asm volatile("mbarrier.init.shared.b64 [%0], %1;"
                     :: "r"(mbar_base + tid * 8), "r"(1) : "memory");
    if (bid < 20 && tid < 10) { spr[tid] = psi_real[tid]; spi[tid] = psi_imag[tid]; }
    __syncthreads();

    // Permuted warp id: remainder chunks (residues 0..232) spread over ALL
    // blocks (wid 0 of every block + wid 1 of blocks 0..84) instead of
    // concentrating 8-deep on blocks 0..29. The strided chunk walk below is
    // unchanged, so the chip-level access pattern is byte-identical to R13.
    int gwarp  = wid * NBLK + bid;
    int stride = NWARPS;                        // 1184

    // Issue one 32-row chunk into warp-stage s (single bulk copy, lane 0).
    auto issue = [&](int chunk, int s) {
        if (lane == 0) {
            int rows = batch - chunk * ROWS_W;
            if (rows > ROWS_W) rows = ROWS_W;
            unsigned bytes = (unsigned)rows * 400u;
            unsigned mb = wmbar + s * 8;
            asm volatile("mbarrier.arrive.expect_tx.shared.b64 _, [%0], %1;"
                         :: "r"(mb), "r"(bytes) : "memory");
            unsigned dst = (unsigned)__cvta_generic_to_shared(ws + s * F4_W);
            const float* src = x + (size_t)chunk * (ROWS_W * 100);
            asm volatile("cp.async.bulk.shared::cta.global.mbarrier::complete_tx::bytes "
                         "[%0], [%1], %2, [%3];"
                         :: "r"(dst), "l"(src), "r"(bytes), "r"(mb) : "memory");
        }
    };

    // Prologue: every warp enqueues both stages first (~205KB/SM in flight).
    if (gwarp < nchunks)          issue(gwarp, 0);
    if (gwarp + stride < nchunks) issue(gwarp + stride, 1);

    // Blocks 0..19: compute the (k,i) partial of M (20 coalesced loads per
    // thread), hidden under the TMA flight. A is read once chip-wide (160KB).
    if (bid < 20) {
        if (tid < 100) {
            int k = bid / 10, i = bid - (bid / 10) * 10;
            int a = tid;
            int abase = ((k * 10 + i) * 10) * 100 + a;
            float acc = 0.0f;
            #pragma unroll
            for (int j = 0; j < 10; j++) {
                float wr = spr[i] * spr[j] + spi[i] * spi[j];
                float wi = spr[i] * spi[j] - spi[i] * spr[j];
                acc = fmaf(wr,  __ldg(A_real + abase + j * 100), acc);
                acc = fmaf(-wi, __ldg(A_imag + abase + j * 100), acc);
            }
            atomicAdd(&g_ctrl.M[k * 100 + a], acc);
            __threadfence();                    // order my adds before the flag
        }
        __syncthreads();
        if (tid == 0) atomicExch(&g_ctrl.flags[bid], 1);
    }

    // All blocks: wait for the 20 producer flags (load-only polling on
    // distinct addresses; shadowed by in-flight TMA copies).
    if (tid < 20) {
        const int* f = &g_ctrl.flags[tid];
        int v;
        do {
            asm volatile("ld.global.cg.b32 %0, [%1];" : "=r"(v) : "l"(f));
            if (!v) __nanosleep(64);
        } while (!v);
    }
    __syncthreads();
    __threadfence();
    if (tid < 200) sMf[tid] = __ldcg(&g_ctrl.M[tid]);   // bypass L1
    __syncthreads();

    // Self-reset: last block to finish copying zeroes the control block for
    // the next graph replay (every block already holds M in smem).
    if (tid == 0) {
        __threadfence();                       // my reads precede the arrive
        int v = atomicAdd(&g_ctrl.copied, 1);
        if (v == NBLK - 1) {
            for (int q = 0; q < 200; q++) g_ctrl.M[q] = 0.0f;
            #pragma unroll
            for (int q = 0; q < 20; q++) g_ctrl.flags[q] = 0;
            __threadfence();
            g_ctrl.copied = 0;
            __threadfence();
        }
    }
    const float4* sM4 = reinterpret_cast<const float4*>(sMf);   // [50]

    // Steady loop (R13-identical): warp-private ring, strided chunk walk.
    int cnt = 0;
    for (int c = gwarp; c < nchunks; c += stride, cnt++) {
        int s = cnt & 1;
        unsigned phase = (cnt >> 1) & 1;
        mbar_wait(wmbar + s * 8, phase);

        int row = c * ROWS_W + lane;
        const float4* xr = ws + s * F4_W + lane * 25;
        float s0 = 0.0f, s1 = 0.0f;
        #pragma unroll
        for (int i = 0; i < 25; i++) {
            float4 v  = xr[i];
            float4 m0 = sM4[i];
            float4 m1 = sM4[25 + i];
            s0 = fmaf(v.x, m0.x, s0); s0 = fmaf(v.y, m0.y, s0);
            s0 = fmaf(v.z, m0.z, s0); s0 = fmaf(v.w, m0.w, s0);
            s1 = fmaf(v.x, m1.x, s1); s1 = fmaf(v.y, m1.y, s1);
            s1 = fmaf(v.z, m1.z, s1); s1 = fmaf(v.w, m1.w, s1);
        }
        if (row < batch) out[row] = make_float2(s0, s1);
        __syncwarp();                      // whole warp done reading stage s

        int cn = c + STAGES * stride;
        if (cn < nchunks) issue(cn, s);
    }
}

extern "C" void kernel_launch(void* const* d_in, const int* in_sizes, int n_in,
                              void* d_out, int out_size) {
    const float* x        = (const float*)d_in[0];  // [BATCH, 100]
    const float* A_real   = (const float*)d_in[1];  // [2,10,10,100]
    const float* A_imag   = (const float*)d_in[2];  // [2,10,10,100]
    const float* psi_real = (const float*)d_in[3];  // [10]
    const float* psi_imag = (const float*)d_in[4];  // [10]

    int batch   = in_sizes[0] / 100;
    int nchunks = (batch + ROWS_W - 1) / ROWS_W;

    static bool attr_done = false;
    if (!attr_done) {
        cudaFuncSetAttribute(fused_kernel,
                             cudaFuncAttributeMaxDynamicSharedMemorySize, SMEM_BYTES);
        attr_done = true;
    }

    fused_kernel<<<NBLK, BLOCK_T, SMEM_BYTES>>>(x, A_real, A_imag,
                                                psi_real, psi_imag,
                                                reinterpret_cast<float2*>(d_out),
                                                batch, nchunks);
}

// round 17
// speedup vs baseline: 1.0449x; 1.0128x over previous
#include <cuda_runtime.h>
#include <cstdint>

#define WARPS_PB   8
#define BLOCK_T    256
#define ROWS_W     32                          // rows per warp-stage chunk
#define F4_W       (ROWS_W * 25)               // 800 float4 per stage
#define STAGES     2
#define SMEM_BYTES (WARPS_PB * STAGES * F4_W * 16)   // 204800 B -> 1 block/SM
#define NBLK       148

// Control block. Zero-initialized at module load; self-reset each launch by
// the last block to finish copying M (no per-launch memset node needed).
struct Ctrl {
    int   flags[20];    // one per producer block (k,i): load-only polling
    int   copied;       // blocks that finished copying M to smem
    int   pad[11];
    float M[200];       // M[k*100 + a]
};
__device__ __align__(16) Ctrl g_ctrl;

__device__ __forceinline__ void mbar_wait(unsigned mbar, unsigned phase) {
    unsigned done;
    asm volatile("{\n\t.reg .pred p;\n\t"
                 "mbarrier.try_wait.parity.acquire.cta.shared::cta.b64 p, [%1], %2;\n\t"
                 "selp.b32 %0, 1, 0, p;\n\t}"
                 : "=r"(done) : "r"(mbar), "r"(phase) : "memory");
    while (!done) {
        asm volatile("{\n\t.reg .pred p;\n\t"
                     "mbarrier.try_wait.parity.acquire.cta.shared::cta.b64 p, [%1], %2, 0x989680;\n\t"
                     "selp.b32 %0, 1, 0, p;\n\t}"
                     : "=r"(done) : "r"(mbar), "r"(phase) : "memory");
    }
}

__global__ void __launch_bounds__(BLOCK_T, 1) fused_kernel(
    const float* __restrict__ x,
    const float* __restrict__ A_real,
    const float* __restrict__ A_imag,
    const float* __restrict__ psi_real,
    const float* __restrict__ psi_imag,
    float2* __restrict__ out,
    int batch, int nchunks)
{
    extern __shared__ __align__(128) float4 sx[];   // [WARPS_PB][STAGES][F4_W]
    __shared__ __align__(16) float sMf[200];
    __shared__ float spr[10], spi[10];
    __shared__ __align__(8) unsigned long long mbar_store[WARPS_PB * STAGES];

    int tid  = threadIdx.x;
    int wid  = tid >> 5;
    int lane = tid & 31;
    int bid  = blockIdx.x;

    unsigned mbar_base = (unsigned)__cvta_generic_to_shared(&mbar_store[0]);
    unsigned wmbar = mbar_base + (wid * STAGES) * 8;
    float4* ws = sx + (size_t)wid * (STAGES * F4_W);

    if (tid < WARPS_PB * STAGES)
        asm volatile("mbarrier.init.shared.b64 [%0], %1;"
                     :: "r"(mbar_base + tid * 8), "r"(1) : "memory");
    if (bid < 20 && tid < 10) { spr[tid] = psi_real[tid]; spi[tid] = psi_imag[tid]; }
    __syncthreads();

    // R13 layout, unchanged: block's 8 warps own 8 contiguous chunks, and the
    // strided walk keeps the chip-wide fetch window dense. Measured optimum.
    int gwarp  = bid * WARPS_PB + wid;
    int stride = NBLK * WARPS_PB;               // 1184

    // Issue one 32-row chunk into warp-stage s (single bulk copy, lane 0).
    auto issue = [&](int chunk, int s) {
        if (lane == 0) {
            int rows = batch - chunk * ROWS_W;
            if (rows > ROWS_W) rows = ROWS_W;
            unsigned bytes = (unsigned)rows * 400u;
            unsigned mb = wmbar + s * 8;
            asm volatile("mbarrier.arrive.expect_tx.shared.b64 _, [%0], %1;"
                         :: "r"(mb), "r"(bytes) : "memory");
            unsigned dst = (unsigned)__cvta_generic_to_shared(ws + s * F4_W);
            const float* src = x + (size_t)chunk * (ROWS_W * 100);
            asm volatile("cp.async.bulk.shared::cta.global.mbarrier::complete_tx::bytes "
                         "[%0], [%1], %2, [%3];"
                         :: "r"(dst), "l"(src), "r"(bytes), "r"(mb) : "memory");
        }
    };

    // Prologue: every warp enqueues both stages first (~205KB/SM in flight).
    if (gwarp < nchunks)          issue(gwarp, 0);
    if (gwarp + stride < nchunks) issue(gwarp + stride, 1);

    // Blocks 0..19: compute the (k,i) partial of M (20 coalesced loads per
    // thread), hidden under the TMA flight. A is read once chip-wide (160KB).
    if (bid < 20) {
        if (tid < 100) {
            int k = bid / 10, i = bid - (bid / 10) * 10;
            int a = tid;
            int abase = ((k * 10 + i) * 10) * 100 + a;
            float acc = 0.0f;
            #pragma unroll
            for (int j = 0; j < 10; j++) {
                float wr = spr[i] * spr[j] + spi[i] * spi[j];
                float wi = spr[i] * spi[j] - spi[i] * spr[j];
                acc = fmaf(wr,  __ldg(A_real + abase + j * 100), acc);
                acc = fmaf(-wi, __ldg(A_imag + abase + j * 100), acc);
            }
            atomicAdd(&g_ctrl.M[k * 100 + a], acc);
            __threadfence();                    // order my adds before the flag
        }
        __syncthreads();
        if (tid == 0) atomicExch(&g_ctrl.flags[bid], 1);
    }

    // All blocks: wait for the 20 producer flags (load-only polling on
    // distinct addresses; shadowed by in-flight TMA copies).
    if (tid < 20) {
        const int* f = &g_ctrl.flags[tid];
        int v;
        do {
            asm volatile("ld.global.cg.b32 %0, [%1];" : "=r"(v) : "l"(f));
            if (!v) __nanosleep(64);
        } while (!v);
    }
    __syncthreads();
    __threadfence();
    if (tid < 200) sMf[tid] = __ldcg(&g_ctrl.M[tid]);   // bypass L1
    __syncthreads();

    // Self-reset: last block to finish copying zeroes the control block for
    // the next graph replay (every block already holds M in smem). One
    // uncontended-path atomic per block; off the streaming critical path.
    if (tid == 0) {
        __threadfence();                       // my reads precede the arrive
        int v = atomicAdd(&g_ctrl.copied, 1);
        if (v == NBLK - 1) {
            for (int q = 0; q < 200; q++) g_ctrl.M[q] = 0.0f;
            #pragma unroll
            for (int q = 0; q < 20; q++) g_ctrl.flags[q] = 0;
            __threadfence();
            g_ctrl.copied = 0;
            __threadfence();
        }
    }
    const float4* sM4 = reinterpret_cast<const float4*>(sMf);   // [50]

    // Steady loop (R13-identical): warp-private ring, strided chunk walk.
    int cnt = 0;
    for (int c = gwarp; c < nchunks; c += stride, cnt++) {
        int s = cnt & 1;
        unsigned phase = (cnt >> 1) & 1;
        mbar_wait(wmbar + s * 8, phase);

        int row = c * ROWS_W + lane;
        const float4* xr = ws + s * F4_W + lane * 25;
        float s0 = 0.0f, s1 = 0.0f;
        #pragma unroll
        for (int i = 0; i < 25; i++) {
            float4 v  = xr[i];
            float4 m0 = sM4[i];
            float4 m1 = sM4[25 + i];
            s0 = fmaf(v.x, m0.x, s0); s0 = fmaf(v.y, m0.y, s0);
            s0 = fmaf(v.z, m0.z, s0); s0 = fmaf(v.w, m0.w, s0);
            s1 = fmaf(v.x, m1.x, s1); s1 = fmaf(v.y, m1.y, s1);
            s1 = fmaf(v.z, m1.z, s1); s1 = fmaf(v.w, m1.w, s1);
        }
        if (row < batch) out[row] = make_float2(s0, s1);
        __syncwarp();                      // whole warp done reading stage s

        int cn = c + STAGES * stride;
        if (cn < nchunks) issue(cn, s);
    }
}

extern "C" void kernel_launch(void* const* d_in, const int* in_sizes, int n_in,
                              void* d_out, int out_size) {
    const float* x        = (const float*)d_in[0];  // [BATCH, 100]
    const float* A_real   = (const float*)d_in[1];  // [2,10,10,100]
    const float* A_imag   = (const float*)d_in[2];  // [2,10,10,100]
    const float* psi_real = (const float*)d_in[3];  // [10]
    const float* psi_imag = (const float*)d_in[4];  // [10]

    int batch   = in_sizes[0] / 100;
    int nchunks = (batch + ROWS_W - 1) / ROWS_W;

    static bool attr_done = false;
    if (!attr_done) {
        cudaFuncSetAttribute(fused_kernel,
                             cudaFuncAttributeMaxDynamicSharedMemorySize, SMEM_BYTES);
        attr_done = true;
    }

    fused_kernel<<<NBLK, BLOCK_T, SMEM_BYTES>>>(x, A_real, A_imag,
                                                psi_real, psi_imag,
                                                reinterpret_cast<float2*>(d_out),
                                                batch, nchunks);
}